// round 8
// baseline (speedup 1.0000x reference)
#include <cuda_runtime.h>

// IAF spiking layer forward; vmem matches XLA ReduceWindowRewriter's scan
// association (base_length = 16) for cumsum over T=512:
//
//   i = 16k + c,  k = 16s + r
//   I[i]   = sequential prefix of x within block k        (leading 0 exact)
//   T_k    = I at block end
//   SPin_k = sequential prefix of T within superblock s   (leading 0 exact)
//   C_k    = add(ET_s, SPin_k), ET_s = exclusive top prefix (0 or U0=SPin_15)
//   E_k    = C_{k-1}  (E_0 = 0)
//   vmem[i] = add(E_k, I[i])     -- single rounded add
//
//   s_t = ((vmem_t - sub) - 1.0 >= 0);  sub += s_t   (sub integer-exact)
//
// One thread per (b, f); coalesced across f, sequential over t.

#define T_SIM 512
#define FEAT  8192

__global__ __launch_bounds__(256, 4)
void iaf_kernel(const float* __restrict__ x, float* __restrict__ out)
{
    const int f = blockIdx.x * blockDim.x + threadIdx.x;
    const int b = blockIdx.y;

    const long long base = (long long)b * T_SIM * FEAT + f;
    const float* __restrict__ xp = x + base;
    float* __restrict__ op = out + base;

    float E    = 0.0f;   // exclusive block prefix (materialized C_{k-1})
    float ET   = 0.0f;   // exclusive superblock prefix (0, then U0)
    float SPin = 0.0f;   // sequential fold of block totals in current superblock
    float sub  = 0.0f;   // accumulated membrane subtraction (integer, exact)

    for (int k = 0; k < 32; ++k) {               // 32 blocks of 16 timesteps
        const float* __restrict__ xb = xp + (long long)k * 16 * FEAT;
        float* __restrict__ ob = op + (long long)k * 16 * FEAT;

        float I = 0.0f;                          // in-block sequential prefix
        #pragma unroll
        for (int c = 0; c < 16; ++c) {
            I = I + xb[c * FEAT];                // leading 0+x exact
            float v = E + I;                     // single add, E=0 exact for k=0
            float u = (v - sub) - 1.0f;
            float s = (u >= 0.0f) ? 1.0f : 0.0f;
            sub += s;
            ob[c * FEAT] = s;
        }

        // block boundary: T_k = I
        SPin = SPin + I;                         // sequential fold of T's
        if (k == 15) {
            ET   = SPin;                         // U0 = C_15 = 0 + SPin (exact)
            E    = ET;                           // E_16 = C_15
            SPin = 0.0f;                         // reset for superblock 1
        } else {
            E = ET + SPin;                       // C_k = add(ET, SPin)
        }
    }
}

extern "C" void kernel_launch(void* const* d_in, const int* in_sizes, int n_in,
                              void* d_out, int out_size)
{
    const float* x = (const float*)d_in[0];
    float* out = (float*)d_out;

    int total = in_sizes[0];
    int batch = total / (T_SIM * FEAT);

    dim3 block(256, 1, 1);
    dim3 grid(FEAT / 256, batch, 1);
    iaf_kernel<<<grid, block>>>(x, out);
}